// round 2
// baseline (speedup 1.0000x reference)
#include <cuda_runtime.h>
#include <math.h>

#define T_STEPS 1024
#define BATCH   256
#define E_DIM   128
#define INP     256
#define G4      512

// 512 MB scratch for x_proj[t][b][g] (fp32, sanctioned __device__ global scratch)
__device__ float g_xproj[134217728];

// ---------------------------------------------------------------------------
// Kernel 1: x_proj = x @ W_ih^T + (b_ih + b_hh)
// A: [M=262144, 256] row-major, W: [512, 256] row-major, C: [M, 512]
// Classic 128x128x16 SGEMM, 256 threads, 8x8 microtile.
// ---------------------------------------------------------------------------
__global__ __launch_bounds__(256, 2)
void xproj_gemm(const float* __restrict__ A,
                const float* __restrict__ W,
                const float* __restrict__ bih,
                const float* __restrict__ bhh)
{
    const int PITCH = 132;                 // floats; multiple of 4 for aligned float4
    __shared__ float As[16 * 132];         // [k][m]
    __shared__ float Bs[16 * 132];         // [k][n]

    const int n0  = blockIdx.x * 128;
    const int m0  = blockIdx.y * 128;
    const int tid = threadIdx.x;
    const int tx  = tid & 15;
    const int ty  = tid >> 4;

    float acc[8][8];
#pragma unroll
    for (int i = 0; i < 8; i++)
#pragma unroll
        for (int j = 0; j < 8; j++) acc[i][j] = 0.f;

    for (int kt = 0; kt < 256; kt += 16) {
#pragma unroll
        for (int ld = 0; ld < 2; ld++) {
            int idx = tid + ld * 256;      // 0..511
            int row = idx >> 2;            // 0..127
            int kk  = (idx & 3) << 2;      // 0,4,8,12
            float4 av = *reinterpret_cast<const float4*>(
                &A[(size_t)(m0 + row) * 256 + kt + kk]);
            As[(kk + 0) * PITCH + row] = av.x;
            As[(kk + 1) * PITCH + row] = av.y;
            As[(kk + 2) * PITCH + row] = av.z;
            As[(kk + 3) * PITCH + row] = av.w;
            float4 bv = *reinterpret_cast<const float4*>(
                &W[(size_t)(n0 + row) * 256 + kt + kk]);
            Bs[(kk + 0) * PITCH + row] = bv.x;
            Bs[(kk + 1) * PITCH + row] = bv.y;
            Bs[(kk + 2) * PITCH + row] = bv.z;
            Bs[(kk + 3) * PITCH + row] = bv.w;
        }
        __syncthreads();
#pragma unroll
        for (int k = 0; k < 16; k++) {
            float a[8], b[8];
            *reinterpret_cast<float4*>(a)     = *reinterpret_cast<const float4*>(&As[k * PITCH + ty * 8]);
            *reinterpret_cast<float4*>(a + 4) = *reinterpret_cast<const float4*>(&As[k * PITCH + ty * 8 + 4]);
            *reinterpret_cast<float4*>(b)     = *reinterpret_cast<const float4*>(&Bs[k * PITCH + tx * 8]);
            *reinterpret_cast<float4*>(b + 4) = *reinterpret_cast<const float4*>(&Bs[k * PITCH + tx * 8 + 4]);
#pragma unroll
            for (int i = 0; i < 8; i++)
#pragma unroll
                for (int j = 0; j < 8; j++)
                    acc[i][j] = fmaf(a[i], b[j], acc[i][j]);
        }
        __syncthreads();
    }

    float bias[8];
#pragma unroll
    for (int j = 0; j < 8; j++)
        bias[j] = bih[n0 + tx * 8 + j] + bhh[n0 + tx * 8 + j];

#pragma unroll
    for (int i = 0; i < 8; i++) {
        float4 o0, o1;
        o0.x = acc[i][0] + bias[0]; o0.y = acc[i][1] + bias[1];
        o0.z = acc[i][2] + bias[2]; o0.w = acc[i][3] + bias[3];
        o1.x = acc[i][4] + bias[4]; o1.y = acc[i][5] + bias[5];
        o1.z = acc[i][6] + bias[6]; o1.w = acc[i][7] + bias[7];
        size_t crow = (size_t)(m0 + ty * 8 + i) * 512 + n0 + tx * 8;
        *reinterpret_cast<float4*>(&g_xproj[crow])     = o0;
        *reinterpret_cast<float4*>(&g_xproj[crow + 4]) = o1;
    }
}

// ---------------------------------------------------------------------------
// Kernel 2: persistent LSTM recurrence. 128 CTAs x 256 threads, 2 batches/CTA.
// W_hh K-split: k in [0,108) in shared (chunk-transposed float4[27][512]),
// k in [108,128) in 40 registers per thread. Thread t owns gates {t, t+256}.
// ---------------------------------------------------------------------------
#define KSH 108
#define NCH 27

__device__ __forceinline__ float fast_sigmoid(float x) {
    return __fdividef(1.f, 1.f + __expf(-x));
}
__device__ __forceinline__ float fast_tanh(float x) {
    float e = __expf(2.f * x);
    return 1.f - __fdividef(2.f, e + 1.f);
}

__global__ __launch_bounds__(256, 1)
void lstm_rec(const float* __restrict__ Whh,
              const float* __restrict__ h0,
              const float* __restrict__ c0,
              float* __restrict__ out)
{
    extern __shared__ float smem[];
    float4* Wsh  = reinterpret_cast<float4*>(smem);   // [NCH][512] float4
    float* gates = smem + NCH * 2048;                 // [2][512]
    float* hsh   = gates + 1024;                      // [2][128]

    const int t   = threadIdx.x;   // 0..255
    const int blk = blockIdx.x;    // 0..127
    const int ga  = t;
    const int gb  = t + 256;

    // Cooperative load of W_hh k<108 into chunk-transposed shared layout
    for (int idx = t; idx < G4 * KSH; idx += 256) {
        int g = idx / KSH;
        int k = idx - g * KSH;
        smem[(k >> 2) * 2048 + g * 4 + (k & 3)] = Whh[g * 128 + k];
    }
    // K-tail weights in registers
    float wa[20], wb[20];
#pragma unroll
    for (int k = 0; k < 20; k++) {
        wa[k] = Whh[ga * 128 + KSH + k];
        wb[k] = Whh[gb * 128 + KSH + k];
    }

    const int b  = t >> 7;         // 0..1
    const int e  = t & 127;        // 0..127
    const int bg = blk * 2 + b;    // global batch index for epilogue role
    hsh[b * 128 + e] = h0[bg * 128 + e];
    float creg = c0[bg * 128 + e];
    __syncthreads();

    const float* xp0 = g_xproj + (size_t)(blk * 2) * 512;
    const float* xp1 = g_xproj + (size_t)(blk * 2 + 1) * 512;
    float* outp = out + (size_t)bg * E_DIM + e;

    const float4* h0v = reinterpret_cast<const float4*>(hsh);
    const float4* h1v = reinterpret_cast<const float4*>(hsh + 128);

    for (int step = 0; step < T_STEPS; step++) {
        size_t soff = (size_t)step * (BATCH * G4);
        float xa0 = xp0[soff + ga];
        float xb0 = xp0[soff + gb];
        float xa1 = xp1[soff + ga];
        float xb1 = xp1[soff + gb];

        float a00 = 0.f, a01 = 0.f, a10 = 0.f, a11 = 0.f;
#pragma unroll
        for (int c = 0; c < NCH; c++) {
            float4 w0  = Wsh[c * 512 + ga];
            float4 w1  = Wsh[c * 512 + gb];
            float4 hv0 = h0v[c];
            float4 hv1 = h1v[c];
            a00 = fmaf(w0.x, hv0.x, a00); a00 = fmaf(w0.y, hv0.y, a00);
            a00 = fmaf(w0.z, hv0.z, a00); a00 = fmaf(w0.w, hv0.w, a00);
            a01 = fmaf(w0.x, hv1.x, a01); a01 = fmaf(w0.y, hv1.y, a01);
            a01 = fmaf(w0.z, hv1.z, a01); a01 = fmaf(w0.w, hv1.w, a01);
            a10 = fmaf(w1.x, hv0.x, a10); a10 = fmaf(w1.y, hv0.y, a10);
            a10 = fmaf(w1.z, hv0.z, a10); a10 = fmaf(w1.w, hv0.w, a10);
            a11 = fmaf(w1.x, hv1.x, a11); a11 = fmaf(w1.y, hv1.y, a11);
            a11 = fmaf(w1.z, hv1.z, a11); a11 = fmaf(w1.w, hv1.w, a11);
        }
        // K-tail from registers (k = 108..127, h via float4 chunks 27..31)
#pragma unroll
        for (int c = 0; c < 5; c++) {
            float4 hv0 = h0v[NCH + c];
            float4 hv1 = h1v[NCH + c];
            a00 = fmaf(wa[4*c+0], hv0.x, a00); a00 = fmaf(wa[4*c+1], hv0.y, a00);
            a00 = fmaf(wa[4*c+2], hv0.z, a00); a00 = fmaf(wa[4*c+3], hv0.w, a00);
            a01 = fmaf(wa[4*c+0], hv1.x, a01); a01 = fmaf(wa[4*c+1], hv1.y, a01);
            a01 = fmaf(wa[4*c+2], hv1.z, a01); a01 = fmaf(wa[4*c+3], hv1.w, a01);
            a10 = fmaf(wb[4*c+0], hv0.x, a10); a10 = fmaf(wb[4*c+1], hv0.y, a10);
            a10 = fmaf(wb[4*c+2], hv0.z, a10); a10 = fmaf(wb[4*c+3], hv0.w, a10);
            a11 = fmaf(wb[4*c+0], hv1.x, a11); a11 = fmaf(wb[4*c+1], hv1.y, a11);
            a11 = fmaf(wb[4*c+2], hv1.z, a11); a11 = fmaf(wb[4*c+3], hv1.w, a11);
        }
        gates[ga]       = a00 + xa0;
        gates[512 + ga] = a01 + xa1;
        gates[gb]       = a10 + xb0;
        gates[512 + gb] = a11 + xb1;
        __syncthreads();

        // Epilogue: thread (b, e)
        float gi = gates[b * 512 + e];
        float gf = gates[b * 512 + 128 + e];
        float gg = gates[b * 512 + 256 + e];
        float go = gates[b * 512 + 384 + e];
        float i_ = fast_sigmoid(gi);
        float f_ = fast_sigmoid(gf);
        float g_ = fast_tanh(gg);
        float o_ = fast_sigmoid(go);
        creg = f_ * creg + i_ * g_;
        float h = o_ * fast_tanh(creg);
        hsh[b * 128 + e] = h;
        outp[(size_t)step * (BATCH * E_DIM)] = log1pf(__expf(h));
        __syncthreads();
    }
}

// ---------------------------------------------------------------------------
extern "C" void kernel_launch(void* const* d_in, const int* in_sizes, int n_in,
                              void* d_out, int out_size)
{
    const float* x   = (const float*)d_in[0];  // [1024,256,256]
    const float* h0  = (const float*)d_in[1];  // [256,128]
    const float* c0  = (const float*)d_in[2];  // [256,128]
    const float* Wih = (const float*)d_in[3];  // [512,256]
    const float* Whh = (const float*)d_in[4];  // [512,128]
    const float* bih = (const float*)d_in[5];  // [512]
    const float* bhh = (const float*)d_in[6];  // [512]
    float* out = (float*)d_out;                // [1024,256,128]

    const int smem_bytes = (NCH * 2048 + 1024 + 256) * 4;  // 226304
    cudaFuncSetAttribute((const void*)lstm_rec,
                         cudaFuncAttributeMaxDynamicSharedMemorySize, smem_bytes);

    xproj_gemm<<<dim3(4, 2048), 256>>>(x, Wih, bih, bhh);
    lstm_rec<<<128, 256, smem_bytes>>>(Whh, h0, c0, out);
}

// round 3
// speedup vs baseline: 1.4032x; 1.4032x over previous
#include <cuda_runtime.h>
#include <mma.h>
#include <math.h>

using namespace nvcuda;

#define T_STEPS 1024
#define BATCH   256
#define E_DIM   128
#define G4      512

// 512 MB scratch for x_proj[t][b][g]
__device__ float g_xproj[134217728];

// ---------------------------------------------------------------------------
// Kernel 1: x_proj = x @ W_ih^T + (b_ih + b_hh), tf32 tensor cores (wmma).
// A: [262144, 256] rm, W: [512, 256] rm (acts as B col-major over k), C:[M,512]
// Block tile 128x128x32, 8 warps (2x4), warp tile 64x32 of m16n16k8 frags.
// ---------------------------------------------------------------------------
__global__ __launch_bounds__(256, 2)
void xproj_gemm_tf32(const float* __restrict__ A,
                     const float* __restrict__ W,
                     const float* __restrict__ bih,
                     const float* __restrict__ bhh)
{
    constexpr int AP = 36;   // smem pitch (floats), 144B = 16B multiple
    __shared__ float As[128 * AP];
    __shared__ float Bs[128 * AP];
    __shared__ float BiasT[16 * 132];

    const int n0  = blockIdx.x * 128;
    const int m0  = blockIdx.y * 128;
    const int tid = threadIdx.x;
    const int warp = tid >> 5;
    const int wm = (warp >> 2) * 64;   // 0 or 64
    const int wn = (warp & 3) * 32;    // 0,32,64,96

    // Bias tile: 16 identical rows of (bih+bhh)[n0 .. n0+127]
    for (int i = tid; i < 16 * 128; i += 256) {
        int r = i >> 7, c = i & 127;
        BiasT[r * 132 + c] = bih[n0 + c] + bhh[n0 + c];
    }
    __syncthreads();

    wmma::fragment<wmma::accumulator, 16, 16, 8, float> cf[4][2];
#pragma unroll
    for (int i = 0; i < 4; i++)
#pragma unroll
        for (int j = 0; j < 2; j++)
            wmma::load_matrix_sync(cf[i][j], &BiasT[wn + j * 16], 132, wmma::mem_row_major);
    __syncthreads();

    for (int kt = 0; kt < 256; kt += 32) {
        // load A tile [128][32] and B tile [128 n-rows][32 k]
#pragma unroll
        for (int l = 0; l < 4; l++) {
            int i   = tid + l * 256;       // 0..1023
            int row = i >> 3;
            int kq  = (i & 7) * 4;
            float4 av = *reinterpret_cast<const float4*>(&A[(size_t)(m0 + row) * 256 + kt + kq]);
            *reinterpret_cast<float4*>(&As[row * AP + kq]) = av;
            float4 bv = *reinterpret_cast<const float4*>(&W[(size_t)(n0 + row) * 256 + kt + kq]);
            *reinterpret_cast<float4*>(&Bs[row * AP + kq]) = bv;
        }
        __syncthreads();

#pragma unroll
        for (int kk = 0; kk < 32; kk += 8) {
            wmma::fragment<wmma::matrix_a, 16, 16, 8, wmma::precision::tf32, wmma::row_major> af[4];
            wmma::fragment<wmma::matrix_b, 16, 16, 8, wmma::precision::tf32, wmma::col_major> bf[2];
#pragma unroll
            for (int i = 0; i < 4; i++) {
                wmma::load_matrix_sync(af[i], &As[(wm + i * 16) * AP + kk], AP);
#pragma unroll
                for (int t = 0; t < af[i].num_elements; t++)
                    af[i].x[t] = wmma::__float_to_tf32(af[i].x[t]);
            }
#pragma unroll
            for (int j = 0; j < 2; j++) {
                wmma::load_matrix_sync(bf[j], &Bs[(wn + j * 16) * AP + kk], AP);
#pragma unroll
                for (int t = 0; t < bf[j].num_elements; t++)
                    bf[j].x[t] = wmma::__float_to_tf32(bf[j].x[t]);
            }
#pragma unroll
            for (int i = 0; i < 4; i++)
#pragma unroll
                for (int j = 0; j < 2; j++)
                    wmma::mma_sync(cf[i][j], af[i], bf[j], cf[i][j]);
        }
        __syncthreads();
    }

#pragma unroll
    for (int i = 0; i < 4; i++)
#pragma unroll
        for (int j = 0; j < 2; j++) {
            float* dst = &g_xproj[(size_t)(m0 + wm + i * 16) * 512 + n0 + wn + j * 16];
            wmma::store_matrix_sync(dst, cf[i][j], 512, wmma::mem_row_major);
        }
}

// ---------------------------------------------------------------------------
// Kernel 2: persistent LSTM recurrence, fp32x2 packed math.
// 128 CTAs x 256 threads, 2 batches/CTA. Thread t owns gates {t, t+256} for
// BOTH batches; accumulators packed {b0,b1} via fma.rn.f32x2.
// W_hh split: k<48 shared (chunk-transposed), k in [48,128) in registers.
// h stored interleaved {h_b0[k], h_b1[k]} so broadcast LDS.128 yields packed pairs.
// ---------------------------------------------------------------------------
#define KSH  48
#define NCHS 12   // shared 4-k chunks
#define KRG  80   // register k per gate

typedef unsigned long long u64;

__device__ __forceinline__ u64 pk2(float lo, float hi) {
    u64 r;
    asm("mov.b64 %0, {%1, %2};" : "=l"(r) : "f"(lo), "f"(hi));
    return r;
}
__device__ __forceinline__ u64 pkdup(float v) {
    u64 r;
    asm("mov.b64 %0, {%1, %1};" : "=l"(r) : "f"(v));
    return r;
}
__device__ __forceinline__ void fma2(u64& d, u64 a, u64 b) {
    asm("fma.rn.f32x2 %0, %1, %2, %0;" : "+l"(d) : "l"(a), "l"(b));
}
__device__ __forceinline__ void unpk2(float& lo, float& hi, u64 v) {
    asm("mov.b64 {%0, %1}, %2;" : "=f"(lo), "=f"(hi) : "l"(v));
}
__device__ __forceinline__ float fast_sigmoid(float x) {
    return __fdividef(1.f, 1.f + __expf(-x));
}
__device__ __forceinline__ float fast_tanh(float x) {
    float e = __expf(2.f * x);
    return 1.f - __fdividef(2.f, e + 1.f);
}

__global__ __launch_bounds__(256, 1)
void lstm_rec(const float* __restrict__ Whh,
              const float* __restrict__ h0,
              const float* __restrict__ c0,
              float* __restrict__ out)
{
    extern __shared__ float smem[];
    float4* Wsh4  = reinterpret_cast<float4*>(smem);          // [NCHS][512] float4
    float*  gatesf = smem + NCHS * 2048;                      // [512] float2 -> 1024 floats
    float*  hshf   = gatesf + 1024;                           // [128] float2 -> 256 floats

    const int t   = threadIdx.x;
    const int blk = blockIdx.x;
    const int ga  = t;
    const int gb  = t + 256;

    // Load W_hh k<48 into chunk-transposed shared: smem[(k>>2)*2048 + g*4 + (k&3)]
    for (int idx = t; idx < G4 * KSH; idx += 256) {
        int g = idx / KSH;
        int k = idx - g * KSH;
        smem[(k >> 2) * 2048 + g * 4 + (k & 3)] = Whh[g * 128 + k];
    }
    // register weights k in [48,128)
    float wra[KRG], wrb[KRG];
#pragma unroll
    for (int k = 0; k < KRG; k++) {
        wra[k] = Whh[ga * 128 + KSH + k];
        wrb[k] = Whh[gb * 128 + KSH + k];
    }

    const int b  = t >> 7;        // epilogue role: batch
    const int e  = t & 127;       // epilogue role: hidden index
    const int bg = blk * 2 + b;
    hshf[e * 2 + b] = h0[bg * 128 + e];
    float creg = c0[bg * 128 + e];
    __syncthreads();

    const float* xp0 = g_xproj + (size_t)(blk * 2) * 512;
    const float* xp1 = g_xproj + (size_t)(blk * 2 + 1) * 512;
    float* outp = out + (size_t)bg * E_DIM + e;

    const ulonglong2* hb = reinterpret_cast<const ulonglong2*>(hshf);

    // prefetch xp for step 0
    float cur0 = xp0[ga], cur1 = xp0[gb], cur2 = xp1[ga], cur3 = xp1[gb];

    for (int step = 0; step < T_STEPS; step++) {
        // prefetch next step's xp (overlaps with FMA loop)
        int ns = (step + 1 < T_STEPS) ? step + 1 : step;
        size_t soff = (size_t)ns * (BATCH * G4);
        float nx0 = __ldg(&xp0[soff + ga]);
        float nx1 = __ldg(&xp0[soff + gb]);
        float nx2 = __ldg(&xp1[soff + ga]);
        float nx3 = __ldg(&xp1[soff + gb]);

        u64 accA = pk2(cur0, cur2);   // gate ga: {batch0, batch1}
        u64 accB = pk2(cur1, cur3);   // gate gb: {batch0, batch1}

        // shared-weight chunks: k = 0..47
#pragma unroll
        for (int c = 0; c < NCHS; c++) {
            float4 wA = Wsh4[c * 512 + ga];
            float4 wB = Wsh4[c * 512 + gb];
            ulonglong2 h01 = hb[c * 2];       // packed pairs for k=4c, 4c+1
            ulonglong2 h23 = hb[c * 2 + 1];   // k=4c+2, 4c+3
            fma2(accA, pkdup(wA.x), h01.x);
            fma2(accB, pkdup(wB.x), h01.x);
            fma2(accA, pkdup(wA.y), h01.y);
            fma2(accB, pkdup(wB.y), h01.y);
            fma2(accA, pkdup(wA.z), h23.x);
            fma2(accB, pkdup(wB.z), h23.x);
            fma2(accA, pkdup(wA.w), h23.y);
            fma2(accB, pkdup(wB.w), h23.y);
        }
        // register-weight chunks: k = 48..127
#pragma unroll
        for (int c = 0; c < KRG / 4; c++) {
            int cc = NCHS + c;
            ulonglong2 h01 = hb[cc * 2];
            ulonglong2 h23 = hb[cc * 2 + 1];
            fma2(accA, pkdup(wra[4 * c + 0]), h01.x);
            fma2(accB, pkdup(wrb[4 * c + 0]), h01.x);
            fma2(accA, pkdup(wra[4 * c + 1]), h01.y);
            fma2(accB, pkdup(wrb[4 * c + 1]), h01.y);
            fma2(accA, pkdup(wra[4 * c + 2]), h23.x);
            fma2(accB, pkdup(wrb[4 * c + 2]), h23.x);
            fma2(accA, pkdup(wra[4 * c + 3]), h23.y);
            fma2(accB, pkdup(wrb[4 * c + 3]), h23.y);
        }

        // store packed gates {b0,b1}
        *reinterpret_cast<u64*>(gatesf + ga * 2) = accA;
        *reinterpret_cast<u64*>(gatesf + gb * 2) = accB;
        __syncthreads();

        // epilogue: thread (b, e)
        float gi = gatesf[(0 * 128 + e) * 2 + b];
        float gf = gatesf[(1 * 128 + e) * 2 + b];
        float gg = gatesf[(2 * 128 + e) * 2 + b];
        float go = gatesf[(3 * 128 + e) * 2 + b];
        float i_ = fast_sigmoid(gi);
        float f_ = fast_sigmoid(gf);
        float g_ = fast_tanh(gg);
        float o_ = fast_sigmoid(go);
        creg = f_ * creg + i_ * g_;
        float h = o_ * fast_tanh(creg);
        hshf[e * 2 + b] = h;
        outp[(size_t)step * (BATCH * E_DIM)] = log1pf(__expf(h));
        __syncthreads();

        cur0 = nx0; cur1 = nx1; cur2 = nx2; cur3 = nx3;
    }
}

// ---------------------------------------------------------------------------
extern "C" void kernel_launch(void* const* d_in, const int* in_sizes, int n_in,
                              void* d_out, int out_size)
{
    const float* x   = (const float*)d_in[0];
    const float* h0  = (const float*)d_in[1];
    const float* c0  = (const float*)d_in[2];
    const float* Wih = (const float*)d_in[3];
    const float* Whh = (const float*)d_in[4];
    const float* bih = (const float*)d_in[5];
    const float* bhh = (const float*)d_in[6];
    float* out = (float*)d_out;

    const int smem_bytes = (NCHS * 2048 + 1024 + 256) * 4;  // 103424
    cudaFuncSetAttribute((const void*)lstm_rec,
                         cudaFuncAttributeMaxDynamicSharedMemorySize, smem_bytes);

    xproj_gemm_tf32<<<dim3(4, 2048), 256>>>(x, Wih, bih, bhh);
    lstm_rec<<<128, 256, smem_bytes>>>(Whh, h0, c0, out);
}